// round 8
// baseline (speedup 1.0000x reference)
#include <cuda_runtime.h>
#include <math_constants.h>

#define NB   8
#define NC   3
#define NN   4096
#define KK   10
#define TPB  512          // threads per block; each thread: 2 queries, 1/4 slice
#define QPB  256          // queries per block
#define MLP0 64
#define MLP1 64
#define BUFE 24           // u64 mask-entries per thread
#define WPAD 40           // padded wfold row: 10 x float4 (x,y,z,0)

// dynamic smem layout:
//   float4 cand[4096]        : 65536 B
//   float  w1eff[64*30]      :  7680 B
//   float  wfold[64*40]      : 10240 B
//   float  biasf[64]         :   256 B
//   u64    buf[BUFE][TPB]    : 98304 B
#define SMEM_FLOATS (NN*4 + MLP0*30 + MLP1*WPAD + MLP1)
#define SMEM_BYTES  (SMEM_FLOATS*4 + BUFE*TPB*8)

__device__ __forceinline__ void insert10(float (&d)[KK], int (&ix)[KK],
                                         float v, int m)
{
    bool c_hi = true;                       // caller guarantees v < d[KK-1]
    #pragma unroll
    for (int i = KK - 1; i >= 1; --i) {
        bool c_lo = v < d[i - 1];
        float tn = c_hi ? v : d[i];
        int   ti = c_hi ? m : ix[i];
        d[i]  = c_lo ? d[i - 1]  : tn;
        ix[i] = c_lo ? ix[i - 1] : ti;
        c_hi = c_lo;
    }
    d[0]  = c_hi ? v : d[0];
    ix[0] = c_hi ? m : ix[0];
}

__device__ __forceinline__ void insert10_tb(float (&d)[KK], int (&ix)[KK],
                                            float v, int m)
{
    bool c_hi = (v < d[KK - 1]) || (v == d[KK - 1] && m < ix[KK - 1]);
    #pragma unroll
    for (int i = KK - 1; i >= 1; --i) {
        bool c_lo = (v < d[i - 1]) || (v == d[i - 1] && m < ix[i - 1]);
        float tn = c_hi ? v : d[i];
        int   ti = c_hi ? m : ix[i];
        d[i]  = c_lo ? d[i - 1]  : tn;
        ix[i] = c_lo ? ix[i - 1] : ti;
        c_hi = c_lo;
    }
    d[0]  = c_hi ? v : d[0];
    ix[0] = c_hi ? m : ix[0];
}

__global__ __launch_bounds__(TPB, 1)
void pcms_kernel(const float* __restrict__ pos,
                 const float* __restrict__ w1,
                 const float* __restrict__ b1,
                 const float* __restrict__ w2,
                 const float* __restrict__ b2,
                 float* __restrict__ out)
{
    extern __shared__ float smem[];
    float4* cand  = reinterpret_cast<float4*>(smem);
    float*  w1eff = smem + NN * 4;
    float*  wfold = w1eff + MLP0 * 30;
    float*  biasf = wfold + MLP1 * WPAD;
    unsigned long long* buf =
        reinterpret_cast<unsigned long long*>(smem + SMEM_FLOATS);

    const int tid = threadIdx.x;
    const int b   = blockIdx.x >> 4;          // 16 chunks per batch
    const int n0  = (blockIdx.x & 15) * QPB;

    // ---- stage 0a: candidate table (x, y, z, 0.5*|p|^2) ----
    const float* pb = pos + b * (NC * NN);
    #pragma unroll
    for (int i = 0; i < NN / TPB; ++i) {
        int n = tid + i * TPB;
        float x = pb[n];
        float y = pb[NN + n];
        float z = pb[2 * NN + n];
        cand[n] = make_float4(x, y, z, 0.5f * (x * x + y * y + z * z));
    }

    // ---- stage 0b: fold w1 over the INDS/squeeze mapping -> w1eff[o][r*3+c] ----
    if (tid < MLP0) {
        float acc[30];
        #pragma unroll
        for (int i = 0; i < 30; ++i) acc[i] = 0.f;
        const int STAB[4][2][2] = {
            {{0, 2}, {4, 6}},   // a
            {{3, 5}, {7, 9}},   // d
            {{1, 3}, {5, 7}},   // b
            {{2, 4}, {6, 8}}    // c
        };
        #pragma unroll
        for (int q = 0; q < 4; ++q)
            #pragma unroll
            for (int c = 0; c < 3; ++c)
                #pragma unroll
                for (int i = 0; i < 2; ++i)
                    #pragma unroll
                    for (int j = 0; j < 2; ++j) {
                        int r = STAB[q][i][j];
                        acc[r * 3 + c] += w1[tid * 48 + (q * 3 + c) * 4 + i * 2 + j];
                    }
        #pragma unroll
        for (int i = 0; i < 30; ++i) w1eff[tid * 30 + i] = acc[i];
    }
    __syncthreads();

    // ---- stage 0c: wfold[p][r*4+c] (padded float4 rows) + bias fold ----
    for (int e = tid; e < MLP1 * WPAD; e += TPB) {
        int p = e / WPAD, t = e % WPAD, r = t >> 2, c = t & 3;
        float s = 0.f;
        if (c < 3) {
            #pragma unroll 8
            for (int o = 0; o < MLP0; ++o)
                s = fmaf(w2[p * MLP0 + o], w1eff[o * 30 + r * 3 + c], s);
        }
        wfold[e] = s;
    }
    if (tid < MLP1) {
        float s = b2[tid];
        #pragma unroll 8
        for (int o = 0; o < MLP0; ++o) s = fmaf(w2[tid * MLP0 + o], b1[o], s);
        biasf[tid] = s;
    }
    __syncthreads();

    // ---- stage 1: exact 10-NN; thread = (query pair) x (1/4 slice) ----
    const int sl  = tid & 3;             // slice 0..3
    const int nqa = n0 + 2 * (tid >> 2); // first query of the pair
    const float4 qda = cand[nqa];
    const float4 qdb = cand[nqa + 1];
    const float ax = qda.x, ay = qda.y, az = qda.z;
    const float bx = qdb.x, by = qdb.y, bz = qdb.z;

    float d0[KK], d1[KK];
    int   i0[KK], i1[KK];
    #pragma unroll
    for (int i = 0; i < KK; ++i) {
        d0[i] = CUDART_INF_F; i0[i] = 0;
        d1[i] = CUDART_INF_F; i1[i] = 0;
    }

    unsigned long long* const bbase = buf + tid;
    unsigned long long* bptr = bbase;
    int nent = 0;

    auto flush = [&]() {
        int j = 0;
        while (__any_sync(0xffffffffu, j < nent)) {
            unsigned mk0 = 0, mk1 = 0; int base = 0;
            if (j < nent) {
                unsigned long long pk = bbase[j * TPB];
                base = (int)(pk & 0xffffffffu);
                mk0  = (unsigned)(pk >> 48);
                mk1  = (unsigned)(pk >> 32) & 0xffffu;
            }
            while (__any_sync(0xffffffffu, (mk0 | mk1) != 0u)) {
                if (mk0) {
                    int u = __ffs(mk0) - 1; mk0 &= mk0 - 1;
                    int m = base + 4 * u;
                    float4 cc = cand[m];
                    float v = cc.w;
                    v = fmaf(-ax, cc.x, v);
                    v = fmaf(-ay, cc.y, v);
                    v = fmaf(-az, cc.z, v);
                    if (v < d0[KK - 1]) insert10(d0, i0, v, m);
                } else if (mk1) {
                    int u = __ffs(mk1) - 1; mk1 &= mk1 - 1;
                    int m = base + 4 * u;
                    float4 cc = cand[m];
                    float v = cc.w;
                    v = fmaf(-bx, cc.x, v);
                    v = fmaf(-by, cc.y, v);
                    v = fmaf(-bz, cc.z, v);
                    if (v < d1[KK - 1]) insert10(d1, i1, v, m);
                }
            }
            ++j;
        }
        bptr = bbase;
        nent = 0;
    };

    bool first = true;
    for (int m0 = sl; m0 < NN; m0 += 64) {
        const float k0 = d0[KK - 1];
        const float k1 = d1[KK - 1];
        unsigned mk0 = 0, mk1 = 0;
        #pragma unroll
        for (int u = 0; u < 16; ++u) {
            float4 cc = cand[m0 + 4 * u];
            float t0 = cc.w, t1 = cc.w;
            t0 = fmaf(-ax, cc.x, t0);
            t1 = fmaf(-bx, cc.x, t1);
            t0 = fmaf(-ay, cc.y, t0);
            t1 = fmaf(-by, cc.y, t1);
            t0 = fmaf(-az, cc.z, t0);
            t1 = fmaf(-bz, cc.z, t1);
            if (t0 < k0) mk0 |= (1u << u);
            if (t1 < k1) mk1 |= (1u << u);
        }
        if (mk0 | mk1) {
            *bptr = (((unsigned long long)mk0) << 48)
                  | (((unsigned long long)mk1) << 32)
                  | (unsigned)m0;
            bptr += TPB;
            ++nent;
        }
        // force an early flush after the first block so thresholds go finite,
        // then flush only when the buffer is full.
        if (first || __any_sync(0xffffffffu, nent == BUFE)) { flush(); first = false; }
    }
    flush();   // drain remainder

    // ---- stage 1b: symmetric 4-way merge (shfl-xor strides 1, 2) ----
    #pragma unroll
    for (int st = 1; st <= 2; st <<= 1) {
        float pd[KK]; int pi[KK];
        #pragma unroll
        for (int r = 0; r < KK; ++r) {
            pd[r] = __shfl_xor_sync(0xffffffffu, d0[r], st);
            pi[r] = __shfl_xor_sync(0xffffffffu, i0[r], st);
        }
        #pragma unroll
        for (int r = 0; r < KK; ++r) insert10_tb(d0, i0, pd[r], pi[r]);
        #pragma unroll
        for (int r = 0; r < KK; ++r) {
            pd[r] = __shfl_xor_sync(0xffffffffu, d1[r], st);
            pi[r] = __shfl_xor_sync(0xffffffffu, i1[r], st);
        }
        #pragma unroll
        for (int r = 0; r < KK; ++r) insert10_tb(d1, i1, pd[r], pi[r]);
    }

    // ---- stage 2: gather neighbors + folded matvec (16 outputs per query) ----
    const int p0 = sl * (MLP1 / 4);
    float* opa = out + b * (MLP1 * NN) + nqa;

    {
        float nx[KK], ny[KK], nz[KK];
        #pragma unroll
        for (int r = 0; r < KK; ++r) {
            float4 cc = cand[i0[r]];
            nx[r] = cc.x; ny[r] = cc.y; nz[r] = cc.z;
        }
        #pragma unroll 4
        for (int pj = 0; pj < MLP1 / 4; ++pj) {
            const int p = p0 + pj;
            float acc = biasf[p];
            const float4* wf4 = reinterpret_cast<const float4*>(wfold + p * WPAD);
            #pragma unroll
            for (int r = 0; r < KK; ++r) {
                float4 w = wf4[r];
                acc = fmaf(w.x, nx[r], acc);
                acc = fmaf(w.y, ny[r], acc);
                acc = fmaf(w.z, nz[r], acc);
            }
            opa[p * NN] = acc;
        }
    }
    {
        float nx[KK], ny[KK], nz[KK];
        #pragma unroll
        for (int r = 0; r < KK; ++r) {
            float4 cc = cand[i1[r]];
            nx[r] = cc.x; ny[r] = cc.y; nz[r] = cc.z;
        }
        #pragma unroll 4
        for (int pj = 0; pj < MLP1 / 4; ++pj) {
            const int p = p0 + pj;
            float acc = biasf[p];
            const float4* wf4 = reinterpret_cast<const float4*>(wfold + p * WPAD);
            #pragma unroll
            for (int r = 0; r < KK; ++r) {
                float4 w = wf4[r];
                acc = fmaf(w.x, nx[r], acc);
                acc = fmaf(w.y, ny[r], acc);
                acc = fmaf(w.z, nz[r], acc);
            }
            opa[p * NN + 1] = acc;
        }
    }
}

extern "C" void kernel_launch(void* const* d_in, const int* in_sizes, int n_in,
                              void* d_out, int out_size)
{
    const float* pos = (const float*)d_in[0];   // (8, 3, 4096)
    const float* w1  = (const float*)d_in[1];   // (64, 12, 2, 2)
    const float* b1  = (const float*)d_in[2];   // (64,)
    const float* w2  = (const float*)d_in[3];   // (64, 64)
    const float* b2  = (const float*)d_in[4];   // (64,)
    float* out = (float*)d_out;                 // (8, 64, 4096)

    cudaFuncSetAttribute(pcms_kernel, cudaFuncAttributeMaxDynamicSharedMemorySize, SMEM_BYTES);

    dim3 grid(NB * (NN / QPB));   // 128 blocks
    dim3 block(TPB);
    pcms_kernel<<<grid, block, SMEM_BYTES>>>(pos, w1, b1, w2, b2, out);
}

// round 10
// speedup vs baseline: 2.0580x; 2.0580x over previous
#include <cuda_runtime.h>
#include <math_constants.h>

#define NB   8
#define NC   3
#define NN   4096
#define KK   10
#define TPB  512          // worker threads per block (2 per query)
#define QPB  256          // queries per block (sorted positions)
#define MLP0 64
#define MLP1 64
#define BUFN 24
#define WPAD 40
#define NCHUNK 128        // 4096 / 32

// ---- global scratch (device statics are allowed) ----
__device__ float4         g_sorted[NB][NN];
__device__ unsigned short g_sidx[NB][NN];
__device__ float          g_cxmin[NB][NCHUNK];
__device__ float          g_cxmax[NB][NCHUNK];
__device__ float          g_smin[NB][NCHUNK];   // suffix-min of cxmin
__device__ float          g_pmax[NB][NCHUNK];   // prefix-max of cxmax

// ---- kernel A: per-batch counting sort by quantized x + chunk bounds ----
__global__ __launch_bounds__(TPB, 1)
void sort_kernel(const float* __restrict__ pos)
{
    __shared__ unsigned hist[256];
    __shared__ unsigned start[256];
    const int b = blockIdx.x;
    const int tid = threadIdx.x;
    const float* pb = pos + b * (NC * NN);

    if (tid < 256) hist[tid] = 0;
    __syncthreads();

    #pragma unroll
    for (int i = 0; i < NN / TPB; ++i) {
        int n = tid + i * TPB;
        float x = pb[n];
        int u = (int)fminf(fmaxf((x + 4.0f) * 32.0f, 0.0f), 255.0f);
        atomicAdd(&hist[u], 1u);
    }
    __syncthreads();

    if (tid < 32) {
        int base = tid * 8;
        unsigned loc[8], s = 0;
        #pragma unroll
        for (int j = 0; j < 8; ++j) { loc[j] = s; s += hist[base + j]; }
        unsigned inc = s;
        #pragma unroll
        for (int off = 1; off < 32; off <<= 1) {
            unsigned nbr = __shfl_up_sync(0xffffffffu, inc, off);
            if (tid >= off) inc += nbr;
        }
        unsigned ex = inc - s;
        #pragma unroll
        for (int j = 0; j < 8; ++j) start[base + j] = ex + loc[j];
    }
    __syncthreads();

    #pragma unroll
    for (int i = 0; i < NN / TPB; ++i) {
        int n = tid + i * TPB;
        float x = pb[n], y = pb[NN + n], z = pb[2 * NN + n];
        int u = (int)fminf(fmaxf((x + 4.0f) * 32.0f, 0.0f), 255.0f);
        unsigned dst = atomicAdd(&start[u], 1u);
        g_sorted[b][dst] = make_float4(x, y, z, 0.5f * (x * x + y * y + z * z));
        g_sidx[b][dst] = (unsigned short)n;
    }
    __syncthreads();

    if (tid < NCHUNK) {
        float mn = CUDART_INF_F, mx = -CUDART_INF_F;
        #pragma unroll 8
        for (int j = 0; j < 32; ++j) {
            float x = g_sorted[b][tid * 32 + j].x;
            mn = fminf(mn, x);
            mx = fmaxf(mx, x);
        }
        g_cxmin[b][tid] = mn;
        g_cxmax[b][tid] = mx;
    }
    __syncthreads();

    if (tid == 0) {
        float m = CUDART_INF_F;
        for (int c = NCHUNK - 1; c >= 0; --c) {
            m = fminf(m, g_cxmin[b][c]);
            g_smin[b][c] = m;
        }
        float M = -CUDART_INF_F;
        for (int c = 0; c < NCHUNK; ++c) {
            M = fmaxf(M, g_cxmax[b][c]);
            g_pmax[b][c] = M;
        }
    }
}

// ---- kernel B ----
// smem layout (float offsets)
#define OFF_CAND   0                        // float4[4096] = 16384 f
#define OFF_W1EFF  (NN * 4)
#define OFF_WFOLD  (OFF_W1EFF + MLP0 * 30)
#define OFF_BIASF  (OFF_WFOLD + MLP1 * WPAD)
#define OFF_CXMIN  (OFF_BIASF + MLP1)
#define OFF_CXMAX  (OFF_CXMIN + NCHUNK)
#define OFF_SMIN   (OFF_CXMAX + NCHUNK)
#define OFF_PMAX   (OFF_SMIN + NCHUNK)
#define OFF_SIDX   (OFF_PMAX + NCHUNK)      // u16[4096] = 2048 f
#define OFF_BUF    (OFF_SIDX + NN / 2)
#define SMEM_BYTES (OFF_BUF * 4 + BUFN * TPB * 8)

__device__ __forceinline__ void insert10_tb(float (&d)[KK], int (&ix)[KK],
                                            float v, int m)
{
    bool c_hi = (v < d[KK - 1]) || (v == d[KK - 1] && m < ix[KK - 1]);
    #pragma unroll
    for (int i = KK - 1; i >= 1; --i) {
        bool c_lo = (v < d[i - 1]) || (v == d[i - 1] && m < ix[i - 1]);
        float tn = c_hi ? v : d[i];
        int   ti = c_hi ? m : ix[i];
        d[i]  = c_lo ? d[i - 1]  : tn;
        ix[i] = c_lo ? ix[i - 1] : ti;
        c_hi = c_lo;
    }
    d[0]  = c_hi ? v : d[0];
    ix[0] = c_hi ? m : ix[0];
}

__global__ __launch_bounds__(TPB, 1)
void pcms_kernel(const float* __restrict__ pos,
                 const float* __restrict__ w1,
                 const float* __restrict__ b1,
                 const float* __restrict__ w2,
                 const float* __restrict__ b2,
                 float* __restrict__ out)
{
    extern __shared__ float smem[];
    float4*         cand  = reinterpret_cast<float4*>(smem + OFF_CAND);
    float*          w1eff = smem + OFF_W1EFF;
    float*          wfold = smem + OFF_WFOLD;
    float*          biasf = smem + OFF_BIASF;
    float*          cxmin = smem + OFF_CXMIN;
    float*          cxmax = smem + OFF_CXMAX;
    float*          smin  = smem + OFF_SMIN;
    float*          pmax  = smem + OFF_PMAX;
    unsigned short* sidx  = reinterpret_cast<unsigned short*>(smem + OFF_SIDX);
    unsigned long long* buf = reinterpret_cast<unsigned long long*>(smem + OFF_BUF);

    const int tid = threadIdx.x;
    const int b   = blockIdx.x >> 4;
    const int n0  = (blockIdx.x & 15) * QPB;
    const float* pb = pos + b * (NC * NN);

    // ---- load sorted candidates + metadata (shared across all 16 blocks) ----
    #pragma unroll
    for (int i = 0; i < NN / TPB; ++i) {
        int n = tid + i * TPB;
        cand[n] = g_sorted[b][n];
        sidx[n] = g_sidx[b][n];
    }
    if (tid < NCHUNK) {
        cxmin[tid] = g_cxmin[b][tid];
        cxmax[tid] = g_cxmax[b][tid];
        smin[tid]  = g_smin[b][tid];
        pmax[tid]  = g_pmax[b][tid];
    }

    // ---- fold w1 ----
    if (tid < MLP0) {
        float acc[30];
        #pragma unroll
        for (int i = 0; i < 30; ++i) acc[i] = 0.f;
        const int STAB[4][2][2] = {
            {{0, 2}, {4, 6}}, {{3, 5}, {7, 9}},
            {{1, 3}, {5, 7}}, {{2, 4}, {6, 8}}
        };
        #pragma unroll
        for (int q = 0; q < 4; ++q)
            #pragma unroll
            for (int c = 0; c < 3; ++c)
                #pragma unroll
                for (int i = 0; i < 2; ++i)
                    #pragma unroll
                    for (int j = 0; j < 2; ++j)
                        acc[STAB[q][i][j] * 3 + c] +=
                            w1[tid * 48 + (q * 3 + c) * 4 + i * 2 + j];
        #pragma unroll
        for (int i = 0; i < 30; ++i) w1eff[tid * 30 + i] = acc[i];
    }
    __syncthreads();

    for (int e = tid; e < MLP1 * WPAD; e += TPB) {
        int p = e / WPAD, t = e % WPAD, r = t >> 2, c = t & 3;
        float s = 0.f;
        if (c < 3) {
            #pragma unroll 8
            for (int o = 0; o < MLP0; ++o)
                s = fmaf(w2[p * MLP0 + o], w1eff[o * 30 + r * 3 + c], s);
        }
        wfold[e] = s;
    }
    if (tid < MLP1) {
        float s = b2[tid];
        #pragma unroll 8
        for (int o = 0; o < MLP0; ++o) s = fmaf(w2[tid * MLP0 + o], b1[o], s);
        biasf[tid] = s;
    }
    __syncthreads();

    // ---- stage 1: exact 10-NN, center-out sweep with pruning ----
    const int s    = tid & 1;
    const int qpos = n0 + (tid >> 1);
    const float4 qd = cand[qpos];
    const int qorg = sidx[qpos];
    const float qx = qd.x, qy = qd.y, qz = qd.z, hq = qd.w;
    const int cw = qpos >> 5;                  // warp-uniform home chunk

    float dist[KK];
    int   iorg[KK];
    #pragma unroll
    for (int i = 0; i < KK; ++i) { dist[i] = CUDART_INF_F; iorg[i] = 0x7fffffff; }

    float kth = CUDART_INF_F;
    float k8  = CUDART_INF_F;

    unsigned long long* const bbase = buf + tid;
    unsigned long long* const blim  = bbase + (BUFN - 16) * TPB;
    unsigned long long* bptr = bbase;

    auto flush = [&]() {
        const int n = (int)((bptr - bbase) / TPB);
        int j = 0;
        while (__any_sync(0xffffffffu, j < n)) {
            if (j < n) {
                unsigned long long pk = bbase[j * TPB];
                const float v = __int_as_float((int)(pk >> 32));
                const int   ms = (int)(pk & 0xffffffffu);
                if (v <= dist[KK - 1]) insert10_tb(dist, iorg, v, (int)sidx[ms]);
            }
            ++j;
        }
        bptr = bbase;
        kth  = dist[KK - 1];
        k8   = dist[KK - 2];
    };

    auto scan_chunk = [&](int c) {
        const int m0 = c * 32 + s;
        float e[16];
        #pragma unroll
        for (int u = 0; u < 16; ++u) {
            float4 cc = cand[m0 + 2 * u];
            float t = cc.w;
            t = fmaf(-qx, cc.x, t);
            t = fmaf(-qy, cc.y, t);
            e[u] = fmaf(-qz, cc.z, t);
        }
        #pragma unroll
        for (int u = 0; u < 16; ++u) {
            if (e[u] <= kth) {
                *bptr = (((unsigned long long)(unsigned)__float_as_int(e[u])) << 32)
                        | (unsigned)(m0 + 2 * u);
                bptr += TPB;
                kth = fmaxf(k8, e[u]);    // valid upper bound on current 10th
            }
        }
        if (__any_sync(0xffffffffu, bptr >= blim)) flush();
    };

    // right sweep: cw, cw+1, ... (break via exact suffix-min bound)
    for (int c = cw; c < NCHUNK; ++c) {
        float kd2 = fmaxf(2.0f * (kth + hq), 0.0f) * 1.0002f + 1e-6f;
        float lbB = fmaxf(smin[c] - qx, 0.0f);
        if (__all_sync(0xffffffffu, lbB * lbB > kd2)) break;
        float lb  = fmaxf(fmaxf(cxmin[c] - qx, qx - cxmax[c]), 0.0f);
        if (__all_sync(0xffffffffu, lb * lb > kd2)) continue;
        scan_chunk(c);
    }
    // left sweep: cw-1, cw-2, ... (break via exact prefix-max bound)
    for (int c = cw - 1; c >= 0; --c) {
        float kd2 = fmaxf(2.0f * (kth + hq), 0.0f) * 1.0002f + 1e-6f;
        float lbB = fmaxf(qx - pmax[c], 0.0f);
        if (__all_sync(0xffffffffu, lbB * lbB > kd2)) break;
        float lb  = fmaxf(fmaxf(cxmin[c] - qx, qx - cxmax[c]), 0.0f);
        if (__all_sync(0xffffffffu, lb * lb > kd2)) continue;
        scan_chunk(c);
    }
    flush();

    // ---- stage 1b: symmetric pair-merge ----
    {
        float pd[KK]; int pi[KK];
        #pragma unroll
        for (int r = 0; r < KK; ++r) {
            pd[r] = __shfl_xor_sync(0xffffffffu, dist[r], 1);
            pi[r] = __shfl_xor_sync(0xffffffffu, iorg[r], 1);
        }
        #pragma unroll
        for (int r = 0; r < KK; ++r) insert10_tb(dist, iorg, pd[r], pi[r]);
    }

    // ---- stage 2: gather neighbors (gmem, L2-hot) + folded matvec ----
    float nx[KK], ny[KK], nz[KK];
    #pragma unroll
    for (int r = 0; r < KK; ++r) {
        int o = iorg[r];
        nx[r] = pb[o];
        ny[r] = pb[NN + o];
        nz[r] = pb[2 * NN + o];
    }

    const int p0 = s * (MLP1 / 2);
    float* op = out + b * (MLP1 * NN) + qorg;
    #pragma unroll 4
    for (int pj = 0; pj < MLP1 / 2; ++pj) {
        const int p = p0 + pj;
        float acc = biasf[p];
        const float4* wf4 = reinterpret_cast<const float4*>(wfold + p * WPAD);
        #pragma unroll
        for (int r = 0; r < KK; ++r) {
            float4 w = wf4[r];
            acc = fmaf(w.x, nx[r], acc);
            acc = fmaf(w.y, ny[r], acc);
            acc = fmaf(w.z, nz[r], acc);
        }
        op[p * NN] = acc;
    }
}

extern "C" void kernel_launch(void* const* d_in, const int* in_sizes, int n_in,
                              void* d_out, int out_size)
{
    const float* pos = (const float*)d_in[0];   // (8, 3, 4096)
    const float* w1  = (const float*)d_in[1];   // (64, 12, 2, 2)
    const float* b1  = (const float*)d_in[2];   // (64,)
    const float* w2  = (const float*)d_in[3];   // (64, 64)
    const float* b2  = (const float*)d_in[4];   // (64,)
    float* out = (float*)d_out;                 // (8, 64, 4096)

    cudaFuncSetAttribute(pcms_kernel, cudaFuncAttributeMaxDynamicSharedMemorySize, SMEM_BYTES);

    sort_kernel<<<NB, TPB>>>(pos);
    pcms_kernel<<<NB * (NN / QPB), TPB, SMEM_BYTES>>>(pos, w1, b1, w2, b2, out);
}